// round 7
// baseline (speedup 1.0000x reference)
#include <cuda_runtime.h>
#include <cuda_bf16.h>
#include <cstdint>

#define NODES_D 128
#define NMAX 50048        // padded to multiple of 256
#define EMAX 800000

// Scratch (no allocations allowed)
__device__ float g_yl[NMAX * NODES_D];    // aggregated-path plane
__device__ float g_yr[NMAX * NODES_D];    // root-path plane (+bias)
__device__ float g_h1[NMAX * NODES_D];
__device__ float g_h2[NMAX * NODES_D];
__device__ int   g_cnti[NMAX];
__device__ int   g_rp[NMAX + 1];
__device__ int   g_woff[NMAX];
__device__ int2  g_ep[EMAX];

// ===========================================================================
// helpers
// ===========================================================================
__device__ __forceinline__ uint32_t smem_u32(const void* p) {
    uint32_t a;
    asm("{ .reg .u64 t; cvta.to.shared.u64 t, %1; cvt.u32.u64 %0, t; }"
        : "=r"(a) : "l"(p));
    return a;
}

__device__ __forceinline__ void ldm_x4(uint32_t* r, uint32_t addr) {
    asm volatile("ldmatrix.sync.aligned.m8n8.x4.shared.b16 {%0,%1,%2,%3}, [%4];"
                 : "=r"(r[0]), "=r"(r[1]), "=r"(r[2]), "=r"(r[3]) : "r"(addr));
}

__device__ __forceinline__ void mma_bf16(float* d, const uint32_t* a,
                                         const uint32_t* b) {
    asm volatile(
        "mma.sync.aligned.m16n8k16.row.col.f32.bf16.bf16.f32 "
        "{%0,%1,%2,%3}, {%4,%5,%6,%7}, {%8,%9}, {%0,%1,%2,%3};"
        : "+f"(d[0]), "+f"(d[1]), "+f"(d[2]), "+f"(d[3])
        : "r"(a[0]), "r"(a[1]), "r"(a[2]), "r"(a[3]), "r"(b[0]), "r"(b[1]));
}

__device__ __forceinline__ uint32_t pack2(__nv_bfloat16 a, __nv_bfloat16 b) {
    return (uint32_t)__bfloat16_as_ushort(a) |
           ((uint32_t)__bfloat16_as_ushort(b) << 16);
}

__device__ __forceinline__ void split_store(char* hi, char* lo, int off, float4 v) {
    __nv_bfloat16 hx = __float2bfloat16(v.x);
    __nv_bfloat16 hy = __float2bfloat16(v.y);
    __nv_bfloat16 hz = __float2bfloat16(v.z);
    __nv_bfloat16 hw = __float2bfloat16(v.w);
    uint2 hp = make_uint2(pack2(hx, hy), pack2(hz, hw));
    uint2 lp = make_uint2(
        pack2(__float2bfloat16(v.x - __bfloat162float(hx)),
              __float2bfloat16(v.y - __bfloat162float(hy))),
        pack2(__float2bfloat16(v.z - __bfloat162float(hz)),
              __float2bfloat16(v.w - __bfloat162float(hw))));
    *(uint2*)(hi + off) = hp;
    *(uint2*)(lo + off) = lp;
}

// ===========================================================================
// CSR build
// ===========================================================================
__global__ void zero_i(int* __restrict__ p, int n) {
    int i = blockIdx.x * blockDim.x + threadIdx.x;
    if (i < n) p[i] = 0;
}

__global__ void count_k(const int* __restrict__ dst, int* __restrict__ cnti, int E) {
    int e = blockIdx.x * blockDim.x + threadIdx.x;
    if (e < E) atomicAdd(&cnti[dst[e]], 1);
}

// single-block exclusive scan over n counters -> rp, woff; rp[n]=E
__global__ void __launch_bounds__(1024)
scan_all(const int* __restrict__ cnt, int* __restrict__ rp,
         int* __restrict__ woff, int n, int E) {
    __shared__ int wsum[32];
    __shared__ int woffs[32];
    const int tid = threadIdx.x, lane = tid & 31, wid = tid >> 5;
    const int c = (n + 1023) >> 10;
    const int b0 = min(tid * c, n);
    const int b1 = min(b0 + c, n);

    int s = 0;
    for (int i = b0; i < b1; ++i) s += cnt[i];

    int p = s;
#pragma unroll
    for (int o = 1; o < 32; o <<= 1) {
        int y = __shfl_up_sync(0xffffffffu, p, o);
        if (lane >= o) p += y;
    }
    if (lane == 31) wsum[wid] = p;
    __syncthreads();
    if (wid == 0) {
        int w = wsum[lane];
        int pi = w;
#pragma unroll
        for (int o = 1; o < 32; o <<= 1) {
            int y = __shfl_up_sync(0xffffffffu, pi, o);
            if (lane >= o) pi += y;
        }
        woffs[lane] = pi - w;
    }
    __syncthreads();

    int run = woffs[wid] + (p - s);
    for (int i = b0; i < b1; ++i) {
        rp[i] = run;
        woff[i] = run;
        run += cnt[i];
    }
    if (tid == 0) rp[n] = E;
}

__global__ void fill_k(const int* __restrict__ src, const int* __restrict__ dst,
                       const float* __restrict__ ew, int* __restrict__ woff,
                       int2* __restrict__ ep, int E) {
    int e = blockIdx.x * blockDim.x + threadIdx.x;
    if (e < E) {
        int d = dst[e];
        int p = atomicAdd(&woff[d], 1);
        ep[p] = make_int2(src[e], __float_as_int(ew[e]));
    }
}

// ===========================================================================
// HMMA GEMM (transform step): [yl | yr] = h @ [Wl | Wr]^T, yr += bias.
// bf16 hi/lo Dekker split, fp32 acc. Block: 64 rows x BCOLS, 8 warps (2x4),
// warp tile 32 x (BCOLS/4). K=128 in 4 chunks of 32 staged in smem
// (stride 80B, conflict-light ldmatrix), mma.sync m16n8k16.
// BCOLS = 2*DOUT (columns [0,DOUT) -> yl plane, [DOUT,2*DOUT) -> yr plane).
// ===========================================================================
template <int BCOLS>
__global__ void __launch_bounds__(256)
gemm_tg(const float* __restrict__ h, const float* __restrict__ Wl,
        const float* __restrict__ Wr, const float* __restrict__ bias,
        float* __restrict__ yl, float* __restrict__ yr, int n) {
    constexpr int DOUT = BCOLS / 2;
    constexpr int STRIDE = 80;                 // bytes per 32-col bf16 row
    constexpr int WCOL = BCOLS / 4;            // 64 or 32
    constexpr int NG = WCOL / 8;               // n8 groups per warp: 8 or 4
    constexpr int NGP = WCOL / 16;             // ldmatrix pairs: 4 or 2
    constexpr int OFF_ALO = 64 * STRIDE;
    constexpr int OFF_WHI = 2 * 64 * STRIDE;
    constexpr int OFF_WLO = OFF_WHI + BCOLS * STRIDE;
    constexpr int WIT = BCOLS * 8 / 256;       // W float4 loads per thread

    extern __shared__ char smem[];
    const uint32_t sbase = smem_u32(smem);

    const int tid = threadIdx.x;
    const int wid = tid >> 5;
    const int lane = tid & 31;
    const int row0 = blockIdx.x * 64;

    const int mrow0 = (wid & 1) * 32;
    const int ncol0 = (wid >> 1) * WCOL;

    const int sel = lane >> 3;
    const int lr8 = lane & 7;
    uint32_t aOff[2], bOff[NGP];
#pragma unroll
    for (int m = 0; m < 2; ++m)
        aOff[m] = (uint32_t)((mrow0 + m * 16 + (sel & 1) * 8 + lr8) * STRIDE +
                             (sel >> 1) * 16);
#pragma unroll
    for (int g = 0; g < NGP; ++g)
        bOff[g] = (uint32_t)((ncol0 + g * 16 + (sel >> 1) * 8 + lr8) * STRIDE +
                             (sel & 1) * 16);

    float acc[2][NG][4];
#pragma unroll
    for (int m = 0; m < 2; ++m)
#pragma unroll
        for (int g = 0; g < NG; ++g)
#pragma unroll
            for (int q = 0; q < 4; ++q) acc[m][g][q] = 0.f;

    for (int ch = 0; ch < 4; ++ch) {
        const int col0 = ch * 32;
        __syncthreads();

        // stage A chunk: 64 rows x 32 cols (hi/lo)
#pragma unroll
        for (int i = 0; i < 2; ++i) {
            const int idx = tid + i * 256;
            const int r = idx >> 3;
            const int c4 = (idx & 7) * 4;
            float4 v = make_float4(0.f, 0.f, 0.f, 0.f);
            if (row0 + r < n)
                v = *(const float4*)(h + (size_t)(row0 + r) * 128 + col0 + c4);
            split_store(smem, smem + OFF_ALO, r * STRIDE + c4 * 2, v);
        }
        // stage W chunk: BCOLS rows of stacked [Wl; Wr] x 32 cols (hi/lo)
#pragma unroll
        for (int i = 0; i < WIT; ++i) {
            const int idx = tid + i * 256;
            const int r = idx >> 3;
            const int c4 = (idx & 7) * 4;
            const float* wp = (r < DOUT) ? (Wl + (size_t)r * 128)
                                         : (Wr + (size_t)(r - DOUT) * 128);
            float4 v = *(const float4*)(wp + col0 + c4);
            split_store(smem + OFF_WHI, smem + OFF_WLO, r * STRIDE + c4 * 2, v);
        }
        __syncthreads();

#pragma unroll
        for (int kk = 0; kk < 2; ++kk) {
            const uint32_t kb = kk * 32;
            uint32_t ah[2][4], al[2][4];
            ldm_x4(ah[0], sbase + aOff[0] + kb);
            ldm_x4(al[0], sbase + OFF_ALO + aOff[0] + kb);
            ldm_x4(ah[1], sbase + aOff[1] + kb);
            ldm_x4(al[1], sbase + OFF_ALO + aOff[1] + kb);
#pragma unroll
            for (int g = 0; g < NGP; ++g) {
                uint32_t bh[4], bl[4];
                ldm_x4(bh, sbase + OFF_WHI + bOff[g] + kb);
                ldm_x4(bl, sbase + OFF_WLO + bOff[g] + kb);
#pragma unroll
                for (int m = 0; m < 2; ++m) {
                    mma_bf16(acc[m][g * 2],     ah[m], bh);
                    mma_bf16(acc[m][g * 2],     al[m], bh);
                    mma_bf16(acc[m][g * 2],     ah[m], bl);
                    mma_bf16(acc[m][g * 2 + 1], ah[m], bh + 2);
                    mma_bf16(acc[m][g * 2 + 1], al[m], bh + 2);
                    mma_bf16(acc[m][g * 2 + 1], ah[m], bl + 2);
                }
            }
        }
    }

    // epilogue: whole warp writes one plane (col-group 0,1 -> yl; 2,3 -> yr)
    const bool is_yr = (ncol0 >= DOUT);
    float* outp = is_yr ? yr : yl;
    const int cbase = ncol0 - (is_yr ? DOUT : 0);
    const int qrow = lane >> 2;
    const int qcol = (lane & 3) * 2;
#pragma unroll
    for (int m = 0; m < 2; ++m) {
        const int rA = row0 + mrow0 + m * 16 + qrow;
        const int rB = rA + 8;
#pragma unroll
        for (int g = 0; g < NG; ++g) {
            const int c0 = cbase + g * 8 + qcol;
            float b0 = 0.f, b1 = 0.f;
            if (is_yr) { b0 = bias[c0]; b1 = bias[c0 + 1]; }
            if (rA < n) {
                float2 o;
                o.x = acc[m][g][0] + b0;
                o.y = acc[m][g][1] + b1;
                *(float2*)(outp + (size_t)rA * DOUT + c0) = o;
            }
            if (rB < n) {
                float2 o;
                o.x = acc[m][g][2] + b0;
                o.y = acc[m][g][3] + b1;
                *(float2*)(outp + (size_t)rB * DOUT + c0) = o;
            }
        }
    }
}

#define SMEM_G256 (2 * 64 * 80 + 2 * 256 * 80)   // 51200
#define SMEM_G128 (2 * 64 * 80 + 2 * 128 * 80)   // 30720

// ===========================================================================
// gather+combine (layers 1,2): h = leaky(BN(mean(w*yl[src]) + yr[node]))
// one warp per node, lane owns 4 cols (float4), edge loop unrolled x2.
// ===========================================================================
__global__ void __launch_bounds__(256)
gather_bn(const float* __restrict__ yl, const float* __restrict__ yr,
          const int* __restrict__ rp, const int2* __restrict__ ep,
          const float* __restrict__ bng, const float* __restrict__ bnb,
          const float* __restrict__ bnm, const float* __restrict__ bnv,
          float* __restrict__ h, int n) {
    const int node = (blockIdx.x * blockDim.x + threadIdx.x) >> 5;
    const int lane = threadIdx.x & 31;
    if (node >= n) return;

    const int s0 = rp[node];
    const int s1 = rp[node + 1];
    const float* xb = yl + lane * 4;

    float ax = 0.f, ay = 0.f, az = 0.f, aw = 0.f;
    for (int base = s0; base < s1; base += 32) {
        const int m = min(32, s1 - base);
        int2 meta = make_int2(0, 0);
        if (lane < m) meta = ep[base + lane];
        int t = 0;
        for (; t + 2 <= m; t += 2) {
            const int   sA = __shfl_sync(0xffffffffu, meta.x, t);
            const float wA = __int_as_float(__shfl_sync(0xffffffffu, meta.y, t));
            const int   sB = __shfl_sync(0xffffffffu, meta.x, t + 1);
            const float wB = __int_as_float(__shfl_sync(0xffffffffu, meta.y, t + 1));
            const float4 vA = *(const float4*)(xb + (size_t)sA * NODES_D);
            const float4 vB = *(const float4*)(xb + (size_t)sB * NODES_D);
            ax += vA.x * wA + vB.x * wB;
            ay += vA.y * wA + vB.y * wB;
            az += vA.z * wA + vB.z * wB;
            aw += vA.w * wA + vB.w * wB;
        }
        if (t < m) {
            const int   sA = __shfl_sync(0xffffffffu, meta.x, t);
            const float wA = __int_as_float(__shfl_sync(0xffffffffu, meta.y, t));
            const float4 vA = *(const float4*)(xb + (size_t)sA * NODES_D);
            ax += vA.x * wA; ay += vA.y * wA; az += vA.z * wA; aw += vA.w * wA;
        }
    }
    const float inv = 1.0f / fmaxf((float)(s1 - s0), 1.0f);
    const int c0 = lane * 4;
    const float4 r = *(const float4*)(yr + (size_t)node * NODES_D + c0);
    const float4 gv = *(const float4*)(bng + c0);
    const float4 bv = *(const float4*)(bnb + c0);
    const float4 mv = *(const float4*)(bnm + c0);
    const float4 vv = *(const float4*)(bnv + c0);

    float4 o;
    float s0f = gv.x * rsqrtf(vv.x + 1e-5f);
    float s1f = gv.y * rsqrtf(vv.y + 1e-5f);
    float s2f = gv.z * rsqrtf(vv.z + 1e-5f);
    float s3f = gv.w * rsqrtf(vv.w + 1e-5f);
    o.x = (ax * inv + r.x - mv.x) * s0f + bv.x;
    o.y = (ay * inv + r.y - mv.y) * s1f + bv.y;
    o.z = (az * inv + r.z - mv.z) * s2f + bv.z;
    o.w = (aw * inv + r.w - mv.w) * s3f + bv.w;
    o.x = (o.x >= 0.f) ? o.x : 0.1f * o.x;
    o.y = (o.y >= 0.f) ? o.y : 0.1f * o.y;
    o.z = (o.z >= 0.f) ? o.z : 0.1f * o.z;
    o.w = (o.w >= 0.f) ? o.w : 0.1f * o.w;
    *(float4*)(h + (size_t)node * NODES_D + c0) = o;
}

// ===========================================================================
// gather+normalize (layer 3): out = l2norm(mean(w*yl[src]) + yr[node]), D=64
// one warp per node, lane owns 2 cols (float2).
// ===========================================================================
__global__ void __launch_bounds__(256)
gather_fin(const float* __restrict__ yl, const float* __restrict__ yr,
           const int* __restrict__ rp, const int2* __restrict__ ep,
           float* __restrict__ out, int n) {
    const int node = (blockIdx.x * blockDim.x + threadIdx.x) >> 5;
    const int lane = threadIdx.x & 31;
    if (node >= n) return;

    const int s0 = rp[node];
    const int s1 = rp[node + 1];
    const float* xb = yl + lane * 2;

    float ax = 0.f, ay = 0.f;
    for (int base = s0; base < s1; base += 32) {
        const int m = min(32, s1 - base);
        int2 meta = make_int2(0, 0);
        if (lane < m) meta = ep[base + lane];
        int t = 0;
        for (; t + 2 <= m; t += 2) {
            const int   sA = __shfl_sync(0xffffffffu, meta.x, t);
            const float wA = __int_as_float(__shfl_sync(0xffffffffu, meta.y, t));
            const int   sB = __shfl_sync(0xffffffffu, meta.x, t + 1);
            const float wB = __int_as_float(__shfl_sync(0xffffffffu, meta.y, t + 1));
            const float2 vA = *(const float2*)(xb + (size_t)sA * 64);
            const float2 vB = *(const float2*)(xb + (size_t)sB * 64);
            ax += vA.x * wA + vB.x * wB;
            ay += vA.y * wA + vB.y * wB;
        }
        if (t < m) {
            const int   sA = __shfl_sync(0xffffffffu, meta.x, t);
            const float wA = __int_as_float(__shfl_sync(0xffffffffu, meta.y, t));
            const float2 vA = *(const float2*)(xb + (size_t)sA * 64);
            ax += vA.x * wA; ay += vA.y * wA;
        }
    }
    const float inv = 1.0f / fmaxf((float)(s1 - s0), 1.0f);
    const float2 r = *(const float2*)(yr + (size_t)node * 64 + lane * 2);
    float v0 = ax * inv + r.x;
    float v1 = ay * inv + r.y;
    float ss = v0 * v0 + v1 * v1;
#pragma unroll
    for (int o = 16; o; o >>= 1) ss += __shfl_xor_sync(0xffffffffu, ss, o);
    const float sc = 1.0f / fmaxf(sqrtf(ss), 1e-12f);
    float2 o;
    o.x = v0 * sc; o.y = v1 * sc;
    *(float2*)(out + (size_t)node * 64 + lane * 2) = o;
}

// ===========================================================================
extern "C" void kernel_launch(void* const* d_in, const int* in_sizes, int n_in,
                              void* d_out, int out_size) {
    const float* x    = (const float*)d_in[0];
    const int*   ei   = (const int*)d_in[1];   // int32 (JAX canonicalizes int64)
    const float* ew   = (const float*)d_in[2];
    const float* W1l  = (const float*)d_in[3];
    const float* b1   = (const float*)d_in[4];
    const float* W1r  = (const float*)d_in[5];
    const float* W2l  = (const float*)d_in[6];
    const float* b2   = (const float*)d_in[7];
    const float* W2r  = (const float*)d_in[8];
    const float* W3l  = (const float*)d_in[9];
    const float* b3   = (const float*)d_in[10];
    const float* W3r  = (const float*)d_in[11];
    const float* bn1g = (const float*)d_in[12];
    const float* bn1b = (const float*)d_in[13];
    const float* bn1m = (const float*)d_in[14];
    const float* bn1v = (const float*)d_in[15];
    const float* bn2g = (const float*)d_in[16];
    const float* bn2b = (const float*)d_in[17];
    const float* bn2m = (const float*)d_in[18];
    const float* bn2v = (const float*)d_in[19];

    const int n = in_sizes[0] / NODES_D;
    const int e = in_sizes[2];

    float *yl, *yr, *h1, *h2;
    int *cnti, *rp, *woff;
    int2 *ep;
    cudaGetSymbolAddress((void**)&yl, g_yl);
    cudaGetSymbolAddress((void**)&yr, g_yr);
    cudaGetSymbolAddress((void**)&h1, g_h1);
    cudaGetSymbolAddress((void**)&h2, g_h2);
    cudaGetSymbolAddress((void**)&cnti, g_cnti);
    cudaGetSymbolAddress((void**)&rp, g_rp);
    cudaGetSymbolAddress((void**)&woff, g_woff);
    cudaGetSymbolAddress((void**)&ep, g_ep);

    cudaFuncSetAttribute(gemm_tg<256>,
                         cudaFuncAttributeMaxDynamicSharedMemorySize, SMEM_G256);
    cudaFuncSetAttribute(gemm_tg<128>,
                         cudaFuncAttributeMaxDynamicSharedMemorySize, SMEM_G128);

    const int* src = ei;
    const int* dst = ei + e;

    const int eb  = (e + 255) / 256;
    const int nbk = (n + 255) / 256;
    const int gbk = (n + 7) / 8;            // gather: 8 warps/block
    const int gb  = (n + 63) / 64;          // gemm: 64 rows/block

    // ---- CSR build ----
    zero_i<<<nbk, 256>>>(cnti, n);
    count_k<<<eb, 256>>>(dst, cnti, e);
    scan_all<<<1, 1024>>>(cnti, rp, woff, n, e);
    fill_k<<<eb, 256>>>(src, dst, ew, woff, ep, e);

    // ---- Layer 1 ----
    gemm_tg<256><<<gb, 256, SMEM_G256>>>(x, W1l, W1r, b1, yl, yr, n);
    gather_bn<<<gbk, 256>>>(yl, yr, rp, ep, bn1g, bn1b, bn1m, bn1v, h1, n);
    // ---- Layer 2 ----
    gemm_tg<256><<<gb, 256, SMEM_G256>>>(h1, W2l, W2r, b2, yl, yr, n);
    gather_bn<<<gbk, 256>>>(yl, yr, rp, ep, bn2g, bn2b, bn2m, bn2v, h2, n);
    // ---- Layer 3 (+ L2 normalize) ----
    gemm_tg<128><<<gb, 256, SMEM_G128>>>(h2, W3l, W3r, b3, yl, yr, n);
    gather_fin<<<gbk, 256>>>(yl, yr, rp, ep, (float*)d_out, n);
}

// round 8
// speedup vs baseline: 1.0987x; 1.0987x over previous
#include <cuda_runtime.h>
#include <cuda_bf16.h>
#include <cstdint>

#define NODES_D 128
#define NMAX 50048        // padded to multiple of 128
#define EMAX 800000
#define WROWS 640         // packed weight rows: W1l,W1r,W2l,W2r (128 ea) + W3l,W3r (64 ea)

// Scratch (no allocations allowed)
__device__ float g_agg[NMAX * NODES_D];
__device__ float g_h1[NMAX * NODES_D];
__device__ float g_h2[NMAX * NODES_D];
__device__ float g_yl3[NMAX * 64];
__device__ float g_yr3[NMAX * 64];
__device__ int   g_cnti[NMAX];
__device__ int   g_rp[NMAX + 1];
__device__ int   g_woff[NMAX];
__device__ int2  g_ep[EMAX];
__device__ __nv_bfloat16 g_whi[WROWS * NODES_D];
__device__ __nv_bfloat16 g_wlo[WROWS * NODES_D];

// ===========================================================================
// helpers
// ===========================================================================
__device__ __forceinline__ uint32_t smem_u32(const void* p) {
    uint32_t a;
    asm("{ .reg .u64 t; cvta.to.shared.u64 t, %1; cvt.u32.u64 %0, t; }"
        : "=r"(a) : "l"(p));
    return a;
}

__device__ __forceinline__ void ldm_x4(uint32_t* r, uint32_t addr) {
    asm volatile("ldmatrix.sync.aligned.m8n8.x4.shared.b16 {%0,%1,%2,%3}, [%4];"
                 : "=r"(r[0]), "=r"(r[1]), "=r"(r[2]), "=r"(r[3]) : "r"(addr));
}

__device__ __forceinline__ void mma_bf16(float* d, const uint32_t* a,
                                         const uint32_t* b) {
    asm volatile(
        "mma.sync.aligned.m16n8k16.row.col.f32.bf16.bf16.f32 "
        "{%0,%1,%2,%3}, {%4,%5,%6,%7}, {%8,%9}, {%0,%1,%2,%3};"
        : "+f"(d[0]), "+f"(d[1]), "+f"(d[2]), "+f"(d[3])
        : "r"(a[0]), "r"(a[1]), "r"(a[2]), "r"(a[3]), "r"(b[0]), "r"(b[1]));
}

__device__ __forceinline__ uint32_t pack2(__nv_bfloat16 a, __nv_bfloat16 b) {
    return (uint32_t)__bfloat16_as_ushort(a) |
           ((uint32_t)__bfloat16_as_ushort(b) << 16);
}

__device__ __forceinline__ void split4(float4 v, uint2& hp, uint2& lp) {
    __nv_bfloat16 hx = __float2bfloat16(v.x);
    __nv_bfloat16 hy = __float2bfloat16(v.y);
    __nv_bfloat16 hz = __float2bfloat16(v.z);
    __nv_bfloat16 hw = __float2bfloat16(v.w);
    hp = make_uint2(pack2(hx, hy), pack2(hz, hw));
    lp = make_uint2(
        pack2(__float2bfloat16(v.x - __bfloat162float(hx)),
              __float2bfloat16(v.y - __bfloat162float(hy))),
        pack2(__float2bfloat16(v.z - __bfloat162float(hz)),
              __float2bfloat16(v.w - __bfloat162float(hw))));
}

// ===========================================================================
// weight pre-split: 640 packed rows x 128 cols fp32 -> bf16 hi/lo planes
// ===========================================================================
__global__ void wsplit_k(const float* __restrict__ W1l, const float* __restrict__ W1r,
                         const float* __restrict__ W2l, const float* __restrict__ W2r,
                         const float* __restrict__ W3l, const float* __restrict__ W3r,
                         __nv_bfloat16* __restrict__ whi,
                         __nv_bfloat16* __restrict__ wlo) {
    const int idx = blockIdx.x * blockDim.x + threadIdx.x;   // 20480 total
    if (idx >= WROWS * NODES_D / 4) return;
    const int r = idx >> 5;             // 32 float4 per row
    const int c = (idx & 31) * 4;
    const float* srcp;
    if      (r < 128) srcp = W1l + (size_t)r * 128;
    else if (r < 256) srcp = W1r + (size_t)(r - 128) * 128;
    else if (r < 384) srcp = W2l + (size_t)(r - 256) * 128;
    else if (r < 512) srcp = W2r + (size_t)(r - 384) * 128;
    else if (r < 576) srcp = W3l + (size_t)(r - 512) * 128;
    else              srcp = W3r + (size_t)(r - 576) * 128;
    float4 v = *(const float4*)(srcp + c);
    uint2 hp, lp;
    split4(v, hp, lp);
    *(uint2*)(whi + (size_t)r * 128 + c) = hp;
    *(uint2*)(wlo + (size_t)r * 128 + c) = lp;
}

// ===========================================================================
// CSR build
// ===========================================================================
__global__ void zero_i(int* __restrict__ p, int n) {
    int i = blockIdx.x * blockDim.x + threadIdx.x;
    if (i < n) p[i] = 0;
}

__global__ void count_k(const int* __restrict__ dst, int* __restrict__ cnti, int E) {
    int e = blockIdx.x * blockDim.x + threadIdx.x;
    if (e < E) atomicAdd(&cnti[dst[e]], 1);
}

__global__ void __launch_bounds__(1024)
scan_all(const int* __restrict__ cnt, int* __restrict__ rp,
         int* __restrict__ woff, int n, int E) {
    __shared__ int wsum[32];
    __shared__ int woffs[32];
    const int tid = threadIdx.x, lane = tid & 31, wid = tid >> 5;
    const int c = (n + 1023) >> 10;
    const int b0 = min(tid * c, n);
    const int b1 = min(b0 + c, n);

    int s = 0;
    for (int i = b0; i < b1; ++i) s += cnt[i];

    int p = s;
#pragma unroll
    for (int o = 1; o < 32; o <<= 1) {
        int y = __shfl_up_sync(0xffffffffu, p, o);
        if (lane >= o) p += y;
    }
    if (lane == 31) wsum[wid] = p;
    __syncthreads();
    if (wid == 0) {
        int w = wsum[lane];
        int pi = w;
#pragma unroll
        for (int o = 1; o < 32; o <<= 1) {
            int y = __shfl_up_sync(0xffffffffu, pi, o);
            if (lane >= o) pi += y;
        }
        woffs[lane] = pi - w;
    }
    __syncthreads();

    int run = woffs[wid] + (p - s);
    for (int i = b0; i < b1; ++i) {
        rp[i] = run;
        woff[i] = run;
        run += cnt[i];
    }
    if (tid == 0) rp[n] = E;
}

__global__ void fill_k(const int* __restrict__ src, const int* __restrict__ dst,
                       const float* __restrict__ ew, int* __restrict__ woff,
                       int2* __restrict__ ep, int E) {
    int e = blockIdx.x * blockDim.x + threadIdx.x;
    if (e < E) {
        int d = dst[e];
        int p = atomicAdd(&woff[d], 1);
        ep[p] = make_int2(src[e], __float_as_int(ew[e]));
    }
}

// ===========================================================================
// Pull aggregation (layers 1,2): out[node] = mean of w*x[src], 128-wide
// ===========================================================================
__global__ void __launch_bounds__(256)
gather_k(const float* __restrict__ x, const int* __restrict__ rp,
         const int2* __restrict__ ep, float* __restrict__ out, int n) {
    const int node = (blockIdx.x * blockDim.x + threadIdx.x) >> 5;
    const int lane = threadIdx.x & 31;
    if (node >= n) return;

    const int s0 = rp[node];
    const int s1 = rp[node + 1];
    const float* xb = x + lane * 4;

    float ax = 0.f, ay = 0.f, az = 0.f, aw = 0.f;
    for (int base = s0; base < s1; base += 32) {
        const int m = min(32, s1 - base);
        int2 meta = make_int2(0, 0);
        if (lane < m) meta = ep[base + lane];
        int t = 0;
        for (; t + 2 <= m; t += 2) {
            const int   sA = __shfl_sync(0xffffffffu, meta.x, t);
            const float wA = __int_as_float(__shfl_sync(0xffffffffu, meta.y, t));
            const int   sB = __shfl_sync(0xffffffffu, meta.x, t + 1);
            const float wB = __int_as_float(__shfl_sync(0xffffffffu, meta.y, t + 1));
            const float4 vA = *(const float4*)(xb + (size_t)sA * NODES_D);
            const float4 vB = *(const float4*)(xb + (size_t)sB * NODES_D);
            ax += vA.x * wA + vB.x * wB;
            ay += vA.y * wA + vB.y * wB;
            az += vA.z * wA + vB.z * wB;
            aw += vA.w * wA + vB.w * wB;
        }
        if (t < m) {
            const int   sA = __shfl_sync(0xffffffffu, meta.x, t);
            const float wA = __int_as_float(__shfl_sync(0xffffffffu, meta.y, t));
            const float4 vA = *(const float4*)(xb + (size_t)sA * NODES_D);
            ax += vA.x * wA; ay += vA.y * wA; az += vA.z * wA; aw += vA.w * wA;
        }
    }
    const float inv = 1.0f / fmaxf((float)(s1 - s0), 1.0f);
    float4 o;
    o.x = ax * inv; o.y = ay * inv; o.z = az * inv; o.w = aw * inv;
    *(float4*)(out + (size_t)node * NODES_D + lane * 4) = o;
}

// ===========================================================================
// HMMA GEMM (layers 1,2): out = [mean|xin](K=256) @ [Wl|Wr]^T + bias,
// then BN+leaky. 128x128 tile, 8 warps (4x2), warp 32x64.
// W loaded pre-split (bf16 hi/lo) from global. A converted in-kernel.
// smem stride 80B.
// ===========================================================================
#define STRIDE 80
#define OFF_ALO (128 * STRIDE)
#define OFF_WHI (2 * 128 * STRIDE)
#define OFF_WLO (3 * 128 * STRIDE)
#define OFF_MUL (4 * 128 * STRIDE)
#define OFF_ADD (OFF_MUL + 128 * 4)
#define SMEM_L12 (OFF_ADD + 128 * 4)

__global__ void __launch_bounds__(256)
gemm_l12(const float* __restrict__ agg, const float* __restrict__ xin,
         const __nv_bfloat16* __restrict__ whi, const __nv_bfloat16* __restrict__ wlo,
         int wbase,                       // packed row base of Wl (Wr at +128)
         const float* __restrict__ bias,
         const float* __restrict__ bng, const float* __restrict__ bnb,
         const float* __restrict__ bnm, const float* __restrict__ bnv,
         float* __restrict__ out, int n) {
    extern __shared__ char smem[];
    const uint32_t sbase = smem_u32(smem);
    float* s_mul = (float*)(smem + OFF_MUL);
    float* s_add = (float*)(smem + OFF_ADD);

    const int tid = threadIdx.x;
    const int wid = tid >> 5;
    const int lane = tid & 31;
    const int row0 = blockIdx.x * 128;

    if (tid < 128) {
        float s = bng[tid] * rsqrtf(bnv[tid] + 1e-5f);
        s_mul[tid] = s;
        s_add[tid] = (bias[tid] - bnm[tid]) * s + bnb[tid];
    }

    const int mrow0 = (wid & 3) * 32;
    const int ncol0 = (wid >> 2) * 64;

    const int sel = lane >> 3;
    const int lr8 = lane & 7;
    uint32_t aOff[2], bOff[4];
#pragma unroll
    for (int m = 0; m < 2; ++m)
        aOff[m] = (uint32_t)((mrow0 + m * 16 + (sel & 1) * 8 + lr8) * STRIDE +
                             (sel >> 1) * 16);
#pragma unroll
    for (int g = 0; g < 4; ++g)
        bOff[g] = (uint32_t)((ncol0 + g * 16 + (sel >> 1) * 8 + lr8) * STRIDE +
                             (sel & 1) * 16);

    float acc[2][8][4];
#pragma unroll
    for (int m = 0; m < 2; ++m)
#pragma unroll
        for (int g = 0; g < 8; ++g)
#pragma unroll
            for (int q = 0; q < 4; ++q) acc[m][g][q] = 0.f;

    for (int ch = 0; ch < 8; ++ch) {
        const float* aB = (ch < 4) ? agg : xin;
        const int wrow = wbase + ((ch < 4) ? 0 : 128);
        const int col0 = (ch & 3) * 32;

        __syncthreads();

        // stage A chunk (convert fp32 -> hi/lo)
#pragma unroll
        for (int i = 0; i < 4; ++i) {
            const int idx = tid + i * 256;
            const int r = idx >> 3;
            const int c4 = (idx & 7) * 4;
            float4 v = make_float4(0.f, 0.f, 0.f, 0.f);
            if (row0 + r < n)
                v = *(const float4*)(aB + (size_t)(row0 + r) * 128 + col0 + c4);
            uint2 hp, lp;
            split4(v, hp, lp);
            const int off = r * STRIDE + c4 * 2;
            *(uint2*)(smem + off) = hp;
            *(uint2*)(smem + OFF_ALO + off) = lp;
        }
        // stage W chunk (pre-split bf16, plain copy)
#pragma unroll
        for (int i = 0; i < 4; ++i) {
            const int idx = tid + i * 256;
            const int r = idx >> 3;
            const int c4 = (idx & 7) * 4;
            const size_t gofs = (size_t)(wrow + r) * 128 + col0 + c4;
            const int off = r * STRIDE + c4 * 2;
            *(uint2*)(smem + OFF_WHI + off) = *(const uint2*)(whi + gofs);
            *(uint2*)(smem + OFF_WLO + off) = *(const uint2*)(wlo + gofs);
        }
        __syncthreads();

#pragma unroll
        for (int kk = 0; kk < 2; ++kk) {
            const uint32_t kb = kk * 32;
            uint32_t ah[2][4], al[2][4];
            ldm_x4(ah[0], sbase + aOff[0] + kb);
            ldm_x4(al[0], sbase + OFF_ALO + aOff[0] + kb);
            ldm_x4(ah[1], sbase + aOff[1] + kb);
            ldm_x4(al[1], sbase + OFF_ALO + aOff[1] + kb);
#pragma unroll
            for (int g = 0; g < 4; ++g) {
                uint32_t bh[4], bl[4];
                ldm_x4(bh, sbase + OFF_WHI + bOff[g] + kb);
                ldm_x4(bl, sbase + OFF_WLO + bOff[g] + kb);
#pragma unroll
                for (int m = 0; m < 2; ++m) {
                    mma_bf16(acc[m][g * 2],     ah[m], bh);
                    mma_bf16(acc[m][g * 2],     al[m], bh);
                    mma_bf16(acc[m][g * 2],     ah[m], bl);
                    mma_bf16(acc[m][g * 2 + 1], ah[m], bh + 2);
                    mma_bf16(acc[m][g * 2 + 1], al[m], bh + 2);
                    mma_bf16(acc[m][g * 2 + 1], ah[m], bl + 2);
                }
            }
        }
    }

    const int qrow = lane >> 2;
    const int qcol = (lane & 3) * 2;
#pragma unroll
    for (int m = 0; m < 2; ++m) {
        const int rA = row0 + mrow0 + m * 16 + qrow;
        const int rB = rA + 8;
#pragma unroll
        for (int g = 0; g < 8; ++g) {
            const int c0 = ncol0 + g * 8 + qcol;
            const float m0 = s_mul[c0], m1 = s_mul[c0 + 1];
            const float a0 = s_add[c0], a1 = s_add[c0 + 1];
            if (rA < n) {
                float f0 = acc[m][g][0] * m0 + a0;
                float f1 = acc[m][g][1] * m1 + a1;
                float2 o;
                o.x = (f0 >= 0.f) ? f0 : 0.1f * f0;
                o.y = (f1 >= 0.f) ? f1 : 0.1f * f1;
                *(float2*)(out + (size_t)rA * 128 + c0) = o;
            }
            if (rB < n) {
                float f2 = acc[m][g][2] * m0 + a0;
                float f3 = acc[m][g][3] * m1 + a1;
                float2 o;
                o.x = (f2 >= 0.f) ? f2 : 0.1f * f2;
                o.y = (f3 >= 0.f) ? f3 : 0.1f * f3;
                *(float2*)(out + (size_t)rB * 128 + c0) = o;
            }
        }
    }
}

// ===========================================================================
// HMMA GEMM (layer 3, transform-first): [yl3|yr3] = h2 @ [W3l;W3r]^T,
// yr3 += b3. 128 rows x 128 cols (cols 0-63 -> yl3, 64-127 -> yr3), K=128.
// ===========================================================================
#define SMEM_L3 (4 * 128 * STRIDE)

__global__ void __launch_bounds__(256)
gemm_l3(const float* __restrict__ h2,
        const __nv_bfloat16* __restrict__ whi, const __nv_bfloat16* __restrict__ wlo,
        int wbase,                        // packed row base of [W3l;W3r]
        const float* __restrict__ bias,
        float* __restrict__ yl3, float* __restrict__ yr3, int n) {
    extern __shared__ char smem[];
    const uint32_t sbase = smem_u32(smem);

    const int tid = threadIdx.x;
    const int wid = tid >> 5;
    const int lane = tid & 31;
    const int row0 = blockIdx.x * 128;

    const int mrow0 = (wid & 3) * 32;
    const int ncol0 = (wid >> 2) * 64;

    const int sel = lane >> 3;
    const int lr8 = lane & 7;
    uint32_t aOff[2], bOff[4];
#pragma unroll
    for (int m = 0; m < 2; ++m)
        aOff[m] = (uint32_t)((mrow0 + m * 16 + (sel & 1) * 8 + lr8) * STRIDE +
                             (sel >> 1) * 16);
#pragma unroll
    for (int g = 0; g < 4; ++g)
        bOff[g] = (uint32_t)((ncol0 + g * 16 + (sel >> 1) * 8 + lr8) * STRIDE +
                             (sel & 1) * 16);

    float acc[2][8][4];
#pragma unroll
    for (int m = 0; m < 2; ++m)
#pragma unroll
        for (int g = 0; g < 8; ++g)
#pragma unroll
            for (int q = 0; q < 4; ++q) acc[m][g][q] = 0.f;

    for (int ch = 0; ch < 4; ++ch) {
        const int col0 = ch * 32;
        __syncthreads();
#pragma unroll
        for (int i = 0; i < 4; ++i) {
            const int idx = tid + i * 256;
            const int r = idx >> 3;
            const int c4 = (idx & 7) * 4;
            float4 v = make_float4(0.f, 0.f, 0.f, 0.f);
            if (row0 + r < n)
                v = *(const float4*)(h2 + (size_t)(row0 + r) * 128 + col0 + c4);
            uint2 hp, lp;
            split4(v, hp, lp);
            const int off = r * STRIDE + c4 * 2;
            *(uint2*)(smem + off) = hp;
            *(uint2*)(smem + OFF_ALO + off) = lp;
        }
#pragma unroll
        for (int i = 0; i < 4; ++i) {
            const int idx = tid + i * 256;
            const int r = idx >> 3;
            const int c4 = (idx & 7) * 4;
            const size_t gofs = (size_t)(wbase + r) * 128 + col0 + c4;
            const int off = r * STRIDE + c4 * 2;
            *(uint2*)(smem + OFF_WHI + off) = *(const uint2*)(whi + gofs);
            *(uint2*)(smem + OFF_WLO + off) = *(const uint2*)(wlo + gofs);
        }
        __syncthreads();

#pragma unroll
        for (int kk = 0; kk < 2; ++kk) {
            const uint32_t kb = kk * 32;
            uint32_t ah[2][4], al[2][4];
            ldm_x4(ah[0], sbase + aOff[0] + kb);
            ldm_x4(al[0], sbase + OFF_ALO + aOff[0] + kb);
            ldm_x4(ah[1], sbase + aOff[1] + kb);
            ldm_x4(al[1], sbase + OFF_ALO + aOff[1] + kb);
#pragma unroll
            for (int g = 0; g < 4; ++g) {
                uint32_t bh[4], bl[4];
                ldm_x4(bh, sbase + OFF_WHI + bOff[g] + kb);
                ldm_x4(bl, sbase + OFF_WLO + bOff[g] + kb);
#pragma unroll
                for (int m = 0; m < 2; ++m) {
                    mma_bf16(acc[m][g * 2],     ah[m], bh);
                    mma_bf16(acc[m][g * 2],     al[m], bh);
                    mma_bf16(acc[m][g * 2],     ah[m], bl);
                    mma_bf16(acc[m][g * 2 + 1], ah[m], bh + 2);
                    mma_bf16(acc[m][g * 2 + 1], al[m], bh + 2);
                    mma_bf16(acc[m][g * 2 + 1], ah[m], bl + 2);
                }
            }
        }
    }

    const bool is_yr = (ncol0 >= 64);
    float* outp = is_yr ? yr3 : yl3;
    const int qrow = lane >> 2;
    const int qcol = (lane & 3) * 2;
#pragma unroll
    for (int m = 0; m < 2; ++m) {
        const int rA = row0 + mrow0 + m * 16 + qrow;
        const int rB = rA + 8;
#pragma unroll
        for (int g = 0; g < 8; ++g) {
            const int c0 = g * 8 + qcol;              // local col 0..63
            float b0 = 0.f, b1 = 0.f;
            if (is_yr) { b0 = bias[c0]; b1 = bias[c0 + 1]; }
            if (rA < n) {
                float2 o;
                o.x = acc[m][g][0] + b0;
                o.y = acc[m][g][1] + b1;
                *(float2*)(outp + (size_t)rA * 64 + c0) = o;
            }
            if (rB < n) {
                float2 o;
                o.x = acc[m][g][2] + b0;
                o.y = acc[m][g][3] + b1;
                *(float2*)(outp + (size_t)rB * 64 + c0) = o;
            }
        }
    }
}

// ===========================================================================
// gather+normalize (layer 3): out = l2norm(mean(w*yl3[src]) + yr3[node]), D=64
// ===========================================================================
__global__ void __launch_bounds__(256)
gather_fin(const float* __restrict__ yl, const float* __restrict__ yr,
           const int* __restrict__ rp, const int2* __restrict__ ep,
           float* __restrict__ out, int n) {
    const int node = (blockIdx.x * blockDim.x + threadIdx.x) >> 5;
    const int lane = threadIdx.x & 31;
    if (node >= n) return;

    const int s0 = rp[node];
    const int s1 = rp[node + 1];
    const float* xb = yl + lane * 2;

    float ax = 0.f, ay = 0.f;
    for (int base = s0; base < s1; base += 32) {
        const int m = min(32, s1 - base);
        int2 meta = make_int2(0, 0);
        if (lane < m) meta = ep[base + lane];
        int t = 0;
        for (; t + 2 <= m; t += 2) {
            const int   sA = __shfl_sync(0xffffffffu, meta.x, t);
            const float wA = __int_as_float(__shfl_sync(0xffffffffu, meta.y, t));
            const int   sB = __shfl_sync(0xffffffffu, meta.x, t + 1);
            const float wB = __int_as_float(__shfl_sync(0xffffffffu, meta.y, t + 1));
            const float2 vA = *(const float2*)(xb + (size_t)sA * 64);
            const float2 vB = *(const float2*)(xb + (size_t)sB * 64);
            ax += vA.x * wA + vB.x * wB;
            ay += vA.y * wA + vB.y * wB;
        }
        if (t < m) {
            const int   sA = __shfl_sync(0xffffffffu, meta.x, t);
            const float wA = __int_as_float(__shfl_sync(0xffffffffu, meta.y, t));
            const float2 vA = *(const float2*)(xb + (size_t)sA * 64);
            ax += vA.x * wA; ay += vA.y * wA;
        }
    }
    const float inv = 1.0f / fmaxf((float)(s1 - s0), 1.0f);
    const float2 r = *(const float2*)(yr + (size_t)node * 64 + lane * 2);
    float v0 = ax * inv + r.x;
    float v1 = ay * inv + r.y;
    float ss = v0 * v0 + v1 * v1;
#pragma unroll
    for (int o = 16; o; o >>= 1) ss += __shfl_xor_sync(0xffffffffu, ss, o);
    const float sc = 1.0f / fmaxf(sqrtf(ss), 1e-12f);
    float2 o;
    o.x = v0 * sc; o.y = v1 * sc;
    *(float2*)(out + (size_t)node * 64 + lane * 2) = o;
}

// ===========================================================================
extern "C" void kernel_launch(void* const* d_in, const int* in_sizes, int n_in,
                              void* d_out, int out_size) {
    const float* x    = (const float*)d_in[0];
    const int*   ei   = (const int*)d_in[1];   // int32 (JAX canonicalizes int64)
    const float* ew   = (const float*)d_in[2];
    const float* W1l  = (const float*)d_in[3];
    const float* b1   = (const float*)d_in[4];
    const float* W1r  = (const float*)d_in[5];
    const float* W2l  = (const float*)d_in[6];
    const float* b2   = (const float*)d_in[7];
    const float* W2r  = (const float*)d_in[8];
    const float* W3l  = (const float*)d_in[9];
    const float* b3   = (const float*)d_in[10];
    const float* W3r  = (const float*)d_in[11];
    const float* bn1g = (const float*)d_in[12];
    const float* bn1b = (const float*)d_in[13];
    const float* bn1m = (const float*)d_in[14];
    const float* bn1v = (const float*)d_in[15];
    const float* bn2g = (const float*)d_in[16];
    const float* bn2b = (const float*)d_in[17];
    const float* bn2m = (const float*)d_in[18];
    const float* bn2v = (const float*)d_in[19];

    const int n = in_sizes[0] / NODES_D;
    const int e = in_sizes[2];

    float *agg, *h1, *h2, *yl3, *yr3;
    int *cnti, *rp, *woff;
    int2 *ep;
    __nv_bfloat16 *whi, *wlo;
    cudaGetSymbolAddress((void**)&agg, g_agg);
    cudaGetSymbolAddress((void**)&h1, g_h1);
    cudaGetSymbolAddress((void**)&h2, g_h2);
    cudaGetSymbolAddress((void**)&yl3, g_yl3);
    cudaGetSymbolAddress((void**)&yr3, g_yr3);
    cudaGetSymbolAddress((void**)&cnti, g_cnti);
    cudaGetSymbolAddress((void**)&rp, g_rp);
    cudaGetSymbolAddress((void**)&woff, g_woff);
    cudaGetSymbolAddress((void**)&ep, g_ep);
    cudaGetSymbolAddress((void**)&whi, g_whi);
    cudaGetSymbolAddress((void**)&wlo, g_wlo);

    cudaFuncSetAttribute(gemm_l12,
                         cudaFuncAttributeMaxDynamicSharedMemorySize, SMEM_L12);
    cudaFuncSetAttribute(gemm_l3,
                         cudaFuncAttributeMaxDynamicSharedMemorySize, SMEM_L3);

    const int* src = ei;
    const int* dst = ei + e;

    const int eb  = (e + 255) / 256;
    const int nbk = (n + 255) / 256;
    const int gbk = (n + 7) / 8;            // gather: 8 warps/block
    const int gb  = (n + 127) / 128;        // gemm: 128 rows/block

    // ---- weight pre-split + CSR build ----
    wsplit_k<<<80, 256>>>(W1l, W1r, W2l, W2r, W3l, W3r, whi, wlo);
    zero_i<<<nbk, 256>>>(cnti, n);
    count_k<<<eb, 256>>>(dst, cnti, e);
    scan_all<<<1, 1024>>>(cnti, rp, woff, n, e);
    fill_k<<<eb, 256>>>(src, dst, ew, woff, ep, e);

    // ---- Layer 1 ----
    gather_k<<<gbk, 256>>>(x, rp, ep, agg, n);
    gemm_l12<<<gb, 256, SMEM_L12>>>(agg, x, whi, wlo, 0, b1,
                                    bn1g, bn1b, bn1m, bn1v, h1, n);
    // ---- Layer 2 ----
    gather_k<<<gbk, 256>>>(h1, rp, ep, agg, n);
    gemm_l12<<<gb, 256, SMEM_L12>>>(agg, h1, whi, wlo, 256, b2,
                                    bn2g, bn2b, bn2m, bn2v, h2, n);
    // ---- Layer 3 (transform-first + L2 normalize) ----
    gemm_l3<<<gb, 256, SMEM_L3>>>(h2, whi, wlo, 512, b3, yl3, yr3, n);
    gather_fin<<<gbk, 256>>>(yl3, yr3, rp, ep, (float*)d_out, n);
}

// round 9
// speedup vs baseline: 1.3805x; 1.2565x over previous
#include <cuda_runtime.h>
#include <cuda_bf16.h>
#include <cstdint>

#define NODES_D 128
#define NMAX 50048        // padded to multiple of 128
#define EMAX 800000
#define WROWS 640         // packed weight rows: W1l,W1r,W2l,W2r (128 ea) + W3l,W3r (64 ea)

// Scratch (no allocations allowed)
__device__ float g_agg[NMAX * NODES_D];
__device__ float g_h1[NMAX * NODES_D];
__device__ float g_h2[NMAX * NODES_D];
__device__ float g_yl3[NMAX * 64];
__device__ float g_yr3[NMAX * 64];
__device__ int   g_cnti[NMAX];
__device__ int   g_rp[NMAX + 1];
__device__ int   g_woff[NMAX];
__device__ int2  g_ep[EMAX];
__device__ int   g_bsum[64];
__device__ __nv_bfloat16 g_whi[WROWS * NODES_D];
__device__ __nv_bfloat16 g_wlo[WROWS * NODES_D];

// ===========================================================================
// helpers
// ===========================================================================
__device__ __forceinline__ uint32_t smem_u32(const void* p) {
    uint32_t a;
    asm("{ .reg .u64 t; cvta.to.shared.u64 t, %1; cvt.u32.u64 %0, t; }"
        : "=r"(a) : "l"(p));
    return a;
}

__device__ __forceinline__ void ldm_x4(uint32_t* r, uint32_t addr) {
    asm volatile("ldmatrix.sync.aligned.m8n8.x4.shared.b16 {%0,%1,%2,%3}, [%4];"
                 : "=r"(r[0]), "=r"(r[1]), "=r"(r[2]), "=r"(r[3]) : "r"(addr));
}

__device__ __forceinline__ void mma_bf16(float* d, const uint32_t* a,
                                         const uint32_t* b) {
    asm volatile(
        "mma.sync.aligned.m16n8k16.row.col.f32.bf16.bf16.f32 "
        "{%0,%1,%2,%3}, {%4,%5,%6,%7}, {%8,%9}, {%0,%1,%2,%3};"
        : "+f"(d[0]), "+f"(d[1]), "+f"(d[2]), "+f"(d[3])
        : "r"(a[0]), "r"(a[1]), "r"(a[2]), "r"(a[3]), "r"(b[0]), "r"(b[1]));
}

__device__ __forceinline__ uint32_t pack2(__nv_bfloat16 a, __nv_bfloat16 b) {
    return (uint32_t)__bfloat16_as_ushort(a) |
           ((uint32_t)__bfloat16_as_ushort(b) << 16);
}

__device__ __forceinline__ void split4(float4 v, uint2& hp, uint2& lp) {
    __nv_bfloat16 hx = __float2bfloat16(v.x);
    __nv_bfloat16 hy = __float2bfloat16(v.y);
    __nv_bfloat16 hz = __float2bfloat16(v.z);
    __nv_bfloat16 hw = __float2bfloat16(v.w);
    hp = make_uint2(pack2(hx, hy), pack2(hz, hw));
    lp = make_uint2(
        pack2(__float2bfloat16(v.x - __bfloat162float(hx)),
              __float2bfloat16(v.y - __bfloat162float(hy))),
        pack2(__float2bfloat16(v.z - __bfloat162float(hz)),
              __float2bfloat16(v.w - __bfloat162float(hw))));
}

// ===========================================================================
// weight pre-split: 640 packed rows x 128 cols fp32 -> bf16 hi/lo planes
// ===========================================================================
__global__ void wsplit_k(const float* __restrict__ W1l, const float* __restrict__ W1r,
                         const float* __restrict__ W2l, const float* __restrict__ W2r,
                         const float* __restrict__ W3l, const float* __restrict__ W3r,
                         __nv_bfloat16* __restrict__ whi,
                         __nv_bfloat16* __restrict__ wlo) {
    const int idx = blockIdx.x * blockDim.x + threadIdx.x;   // 20480 total
    if (idx >= WROWS * NODES_D / 4) return;
    const int r = idx >> 5;             // 32 float4 per row
    const int c = (idx & 31) * 4;
    const float* srcp;
    if      (r < 128) srcp = W1l + (size_t)r * 128;
    else if (r < 256) srcp = W1r + (size_t)(r - 128) * 128;
    else if (r < 384) srcp = W2l + (size_t)(r - 256) * 128;
    else if (r < 512) srcp = W2r + (size_t)(r - 384) * 128;
    else if (r < 576) srcp = W3l + (size_t)(r - 512) * 128;
    else              srcp = W3r + (size_t)(r - 576) * 128;
    float4 v = *(const float4*)(srcp + c);
    uint2 hp, lp;
    split4(v, hp, lp);
    *(uint2*)(whi + (size_t)r * 128 + c) = hp;
    *(uint2*)(wlo + (size_t)r * 128 + c) = lp;
}

// ===========================================================================
// CSR build
// ===========================================================================
__global__ void zero_i(int* __restrict__ p, int n) {
    int i = blockIdx.x * blockDim.x + threadIdx.x;
    if (i < n) p[i] = 0;
}

__global__ void count_k(const int* __restrict__ dst, int* __restrict__ cnti, int E) {
    int e = blockIdx.x * blockDim.x + threadIdx.x;
    if (e < E) atomicAdd(&cnti[dst[e]], 1);
}

// per-block (1024 items) exclusive scan -> rp, block totals -> bsum
__global__ void scan1_k(const int* __restrict__ cnt, int* __restrict__ rp,
                        int* __restrict__ bsum, int n) {
    __shared__ int ws[8];
    const int tid = threadIdx.x, lane = tid & 31, wid = tid >> 5;
    const int i0 = blockIdx.x * 1024 + tid * 4;
    int v0 = (i0 + 0 < n) ? cnt[i0 + 0] : 0;
    int v1 = (i0 + 1 < n) ? cnt[i0 + 1] : 0;
    int v2 = (i0 + 2 < n) ? cnt[i0 + 2] : 0;
    int v3 = (i0 + 3 < n) ? cnt[i0 + 3] : 0;
    const int t = v0 + v1 + v2 + v3;
    int p = t;
#pragma unroll
    for (int o = 1; o < 32; o <<= 1) {
        int y = __shfl_up_sync(0xffffffffu, p, o);
        if (lane >= o) p += y;
    }
    if (lane == 31) ws[wid] = p;
    __syncthreads();
    if (wid == 0) {
        int w = (lane < 8) ? ws[lane] : 0;
        int pi = w;
#pragma unroll
        for (int o = 1; o < 8; o <<= 1) {
            int y = __shfl_up_sync(0xffffffffu, pi, o);
            if (lane >= o) pi += y;
        }
        if (lane == 7) bsum[blockIdx.x] = pi;
        if (lane < 8) ws[lane] = pi - w;     // exclusive warp offsets
    }
    __syncthreads();
    const int off = ws[wid] + (p - t);
    if (i0 + 0 < n) rp[i0 + 0] = off;
    if (i0 + 1 < n) rp[i0 + 1] = off + v0;
    if (i0 + 2 < n) rp[i0 + 2] = off + v0 + v1;
    if (i0 + 3 < n) rp[i0 + 3] = off + v0 + v1 + v2;
}

__global__ void scan2_k(int* __restrict__ bsum, int nb) {
    const int lane = threadIdx.x;
    int run = 0;
    for (int base = 0; base < nb; base += 32) {
        int v = (base + lane < nb) ? bsum[base + lane] : 0;
        int p = v;
#pragma unroll
        for (int o = 1; o < 32; o <<= 1) {
            int y = __shfl_up_sync(0xffffffffu, p, o);
            if (lane >= o) p += y;
        }
        if (base + lane < nb) bsum[base + lane] = p - v + run;
        run += __shfl_sync(0xffffffffu, p, 31);
    }
}

__global__ void scan3_k(int* __restrict__ rp, int* __restrict__ woff,
                        const int* __restrict__ bsum, int n, int E) {
    int i = blockIdx.x * blockDim.x + threadIdx.x;
    if (i < n) {
        int v = rp[i] + bsum[i >> 10];
        rp[i] = v;
        woff[i] = v;
    }
    if (i == 0) rp[n] = E;
}

__global__ void fill_k(const int* __restrict__ src, const int* __restrict__ dst,
                       const float* __restrict__ ew, int* __restrict__ woff,
                       int2* __restrict__ ep, int E) {
    int e = blockIdx.x * blockDim.x + threadIdx.x;
    if (e < E) {
        int d = dst[e];
        int p = atomicAdd(&woff[d], 1);
        ep[p] = make_int2(src[e], __float_as_int(ew[e]));
    }
}

// ===========================================================================
// Pull aggregation (layers 1,2): out[node] = mean of w*x[src], 128-wide
// ===========================================================================
__global__ void __launch_bounds__(256)
gather_k(const float* __restrict__ x, const int* __restrict__ rp,
         const int2* __restrict__ ep, float* __restrict__ out, int n) {
    const int node = (blockIdx.x * blockDim.x + threadIdx.x) >> 5;
    const int lane = threadIdx.x & 31;
    if (node >= n) return;

    const int s0 = rp[node];
    const int s1 = rp[node + 1];
    const float* xb = x + lane * 4;

    float ax = 0.f, ay = 0.f, az = 0.f, aw = 0.f;
    for (int base = s0; base < s1; base += 32) {
        const int m = min(32, s1 - base);
        int2 meta = make_int2(0, 0);
        if (lane < m) meta = ep[base + lane];
        int t = 0;
        for (; t + 2 <= m; t += 2) {
            const int   sA = __shfl_sync(0xffffffffu, meta.x, t);
            const float wA = __int_as_float(__shfl_sync(0xffffffffu, meta.y, t));
            const int   sB = __shfl_sync(0xffffffffu, meta.x, t + 1);
            const float wB = __int_as_float(__shfl_sync(0xffffffffu, meta.y, t + 1));
            const float4 vA = *(const float4*)(xb + (size_t)sA * NODES_D);
            const float4 vB = *(const float4*)(xb + (size_t)sB * NODES_D);
            ax += vA.x * wA + vB.x * wB;
            ay += vA.y * wA + vB.y * wB;
            az += vA.z * wA + vB.z * wB;
            aw += vA.w * wA + vB.w * wB;
        }
        if (t < m) {
            const int   sA = __shfl_sync(0xffffffffu, meta.x, t);
            const float wA = __int_as_float(__shfl_sync(0xffffffffu, meta.y, t));
            const float4 vA = *(const float4*)(xb + (size_t)sA * NODES_D);
            ax += vA.x * wA; ay += vA.y * wA; az += vA.z * wA; aw += vA.w * wA;
        }
    }
    const float inv = 1.0f / fmaxf((float)(s1 - s0), 1.0f);
    float4 o;
    o.x = ax * inv; o.y = ay * inv; o.z = az * inv; o.w = aw * inv;
    *(float4*)(out + (size_t)node * NODES_D + lane * 4) = o;
}

// ===========================================================================
// HMMA GEMM (layers 1,2): out = [mean|xin](K=256) @ [Wl|Wr]^T + bias,
// then BN+leaky. 128x128 tile, 8 warps (4x2), warp 32x64.
// W loaded pre-split (bf16 hi/lo) from global. A converted in-kernel.
// smem stride 80B.
// ===========================================================================
#define STRIDE 80
#define OFF_ALO (128 * STRIDE)
#define OFF_WHI (2 * 128 * STRIDE)
#define OFF_WLO (3 * 128 * STRIDE)
#define OFF_MUL (4 * 128 * STRIDE)
#define OFF_ADD (OFF_MUL + 128 * 4)
#define SMEM_L12 (OFF_ADD + 128 * 4)

__global__ void __launch_bounds__(256)
gemm_l12(const float* __restrict__ agg, const float* __restrict__ xin,
         const __nv_bfloat16* __restrict__ whi, const __nv_bfloat16* __restrict__ wlo,
         int wbase,                       // packed row base of Wl (Wr at +128)
         const float* __restrict__ bias,
         const float* __restrict__ bng, const float* __restrict__ bnb,
         const float* __restrict__ bnm, const float* __restrict__ bnv,
         float* __restrict__ out, int n) {
    extern __shared__ char smem[];
    const uint32_t sbase = smem_u32(smem);
    float* s_mul = (float*)(smem + OFF_MUL);
    float* s_add = (float*)(smem + OFF_ADD);

    const int tid = threadIdx.x;
    const int wid = tid >> 5;
    const int lane = tid & 31;
    const int row0 = blockIdx.x * 128;

    if (tid < 128) {
        float s = bng[tid] * rsqrtf(bnv[tid] + 1e-5f);
        s_mul[tid] = s;
        s_add[tid] = (bias[tid] - bnm[tid]) * s + bnb[tid];
    }

    const int mrow0 = (wid & 3) * 32;
    const int ncol0 = (wid >> 2) * 64;

    const int sel = lane >> 3;
    const int lr8 = lane & 7;
    uint32_t aOff[2], bOff[4];
#pragma unroll
    for (int m = 0; m < 2; ++m)
        aOff[m] = (uint32_t)((mrow0 + m * 16 + (sel & 1) * 8 + lr8) * STRIDE +
                             (sel >> 1) * 16);
#pragma unroll
    for (int g = 0; g < 4; ++g)
        bOff[g] = (uint32_t)((ncol0 + g * 16 + (sel >> 1) * 8 + lr8) * STRIDE +
                             (sel & 1) * 16);

    float acc[2][8][4];
#pragma unroll
    for (int m = 0; m < 2; ++m)
#pragma unroll
        for (int g = 0; g < 8; ++g)
#pragma unroll
            for (int q = 0; q < 4; ++q) acc[m][g][q] = 0.f;

    for (int ch = 0; ch < 8; ++ch) {
        const float* aB = (ch < 4) ? agg : xin;
        const int wrow = wbase + ((ch < 4) ? 0 : 128);
        const int col0 = (ch & 3) * 32;

        __syncthreads();

        // stage A chunk (convert fp32 -> hi/lo)
#pragma unroll
        for (int i = 0; i < 4; ++i) {
            const int idx = tid + i * 256;
            const int r = idx >> 3;
            const int c4 = (idx & 7) * 4;
            float4 v = make_float4(0.f, 0.f, 0.f, 0.f);
            if (row0 + r < n)
                v = *(const float4*)(aB + (size_t)(row0 + r) * 128 + col0 + c4);
            uint2 hp, lp;
            split4(v, hp, lp);
            const int off = r * STRIDE + c4 * 2;
            *(uint2*)(smem + off) = hp;
            *(uint2*)(smem + OFF_ALO + off) = lp;
        }
        // stage W chunk (pre-split bf16, plain copy)
#pragma unroll
        for (int i = 0; i < 4; ++i) {
            const int idx = tid + i * 256;
            const int r = idx >> 3;
            const int c4 = (idx & 7) * 4;
            const size_t gofs = (size_t)(wrow + r) * 128 + col0 + c4;
            const int off = r * STRIDE + c4 * 2;
            *(uint2*)(smem + OFF_WHI + off) = *(const uint2*)(whi + gofs);
            *(uint2*)(smem + OFF_WLO + off) = *(const uint2*)(wlo + gofs);
        }
        __syncthreads();

#pragma unroll
        for (int kk = 0; kk < 2; ++kk) {
            const uint32_t kb = kk * 32;
            uint32_t ah[2][4], al[2][4];
            ldm_x4(ah[0], sbase + aOff[0] + kb);
            ldm_x4(al[0], sbase + OFF_ALO + aOff[0] + kb);
            ldm_x4(ah[1], sbase + aOff[1] + kb);
            ldm_x4(al[1], sbase + OFF_ALO + aOff[1] + kb);
#pragma unroll
            for (int g = 0; g < 4; ++g) {
                uint32_t bh[4], bl[4];
                ldm_x4(bh, sbase + OFF_WHI + bOff[g] + kb);
                ldm_x4(bl, sbase + OFF_WLO + bOff[g] + kb);
#pragma unroll
                for (int m = 0; m < 2; ++m) {
                    mma_bf16(acc[m][g * 2],     ah[m], bh);
                    mma_bf16(acc[m][g * 2],     al[m], bh);
                    mma_bf16(acc[m][g * 2],     ah[m], bl);
                    mma_bf16(acc[m][g * 2 + 1], ah[m], bh + 2);
                    mma_bf16(acc[m][g * 2 + 1], al[m], bh + 2);
                    mma_bf16(acc[m][g * 2 + 1], ah[m], bl + 2);
                }
            }
        }
    }

    const int qrow = lane >> 2;
    const int qcol = (lane & 3) * 2;
#pragma unroll
    for (int m = 0; m < 2; ++m) {
        const int rA = row0 + mrow0 + m * 16 + qrow;
        const int rB = rA + 8;
#pragma unroll
        for (int g = 0; g < 8; ++g) {
            const int c0 = ncol0 + g * 8 + qcol;
            const float m0 = s_mul[c0], m1 = s_mul[c0 + 1];
            const float a0 = s_add[c0], a1 = s_add[c0 + 1];
            if (rA < n) {
                float f0 = acc[m][g][0] * m0 + a0;
                float f1 = acc[m][g][1] * m1 + a1;
                float2 o;
                o.x = (f0 >= 0.f) ? f0 : 0.1f * f0;
                o.y = (f1 >= 0.f) ? f1 : 0.1f * f1;
                *(float2*)(out + (size_t)rA * 128 + c0) = o;
            }
            if (rB < n) {
                float f2 = acc[m][g][2] * m0 + a0;
                float f3 = acc[m][g][3] * m1 + a1;
                float2 o;
                o.x = (f2 >= 0.f) ? f2 : 0.1f * f2;
                o.y = (f3 >= 0.f) ? f3 : 0.1f * f3;
                *(float2*)(out + (size_t)rB * 128 + c0) = o;
            }
        }
    }
}

// ===========================================================================
// HMMA GEMM (layer 3, transform-first): [yl3|yr3] = h2 @ [W3l;W3r]^T,
// yr3 += b3. 128 rows x 128 cols (cols 0-63 -> yl3, 64-127 -> yr3), K=128.
// ===========================================================================
#define SMEM_L3 (4 * 128 * STRIDE)

__global__ void __launch_bounds__(256)
gemm_l3(const float* __restrict__ h2,
        const __nv_bfloat16* __restrict__ whi, const __nv_bfloat16* __restrict__ wlo,
        int wbase,                        // packed row base of [W3l;W3r]
        const float* __restrict__ bias,
        float* __restrict__ yl3, float* __restrict__ yr3, int n) {
    extern __shared__ char smem[];
    const uint32_t sbase = smem_u32(smem);

    const int tid = threadIdx.x;
    const int wid = tid >> 5;
    const int lane = tid & 31;
    const int row0 = blockIdx.x * 128;

    const int mrow0 = (wid & 3) * 32;
    const int ncol0 = (wid >> 2) * 64;

    const int sel = lane >> 3;
    const int lr8 = lane & 7;
    uint32_t aOff[2], bOff[4];
#pragma unroll
    for (int m = 0; m < 2; ++m)
        aOff[m] = (uint32_t)((mrow0 + m * 16 + (sel & 1) * 8 + lr8) * STRIDE +
                             (sel >> 1) * 16);
#pragma unroll
    for (int g = 0; g < 4; ++g)
        bOff[g] = (uint32_t)((ncol0 + g * 16 + (sel >> 1) * 8 + lr8) * STRIDE +
                             (sel & 1) * 16);

    float acc[2][8][4];
#pragma unroll
    for (int m = 0; m < 2; ++m)
#pragma unroll
        for (int g = 0; g < 8; ++g)
#pragma unroll
            for (int q = 0; q < 4; ++q) acc[m][g][q] = 0.f;

    for (int ch = 0; ch < 4; ++ch) {
        const int col0 = ch * 32;
        __syncthreads();
#pragma unroll
        for (int i = 0; i < 4; ++i) {
            const int idx = tid + i * 256;
            const int r = idx >> 3;
            const int c4 = (idx & 7) * 4;
            float4 v = make_float4(0.f, 0.f, 0.f, 0.f);
            if (row0 + r < n)
                v = *(const float4*)(h2 + (size_t)(row0 + r) * 128 + col0 + c4);
            uint2 hp, lp;
            split4(v, hp, lp);
            const int off = r * STRIDE + c4 * 2;
            *(uint2*)(smem + off) = hp;
            *(uint2*)(smem + OFF_ALO + off) = lp;
        }
#pragma unroll
        for (int i = 0; i < 4; ++i) {
            const int idx = tid + i * 256;
            const int r = idx >> 3;
            const int c4 = (idx & 7) * 4;
            const size_t gofs = (size_t)(wbase + r) * 128 + col0 + c4;
            const int off = r * STRIDE + c4 * 2;
            *(uint2*)(smem + OFF_WHI + off) = *(const uint2*)(whi + gofs);
            *(uint2*)(smem + OFF_WLO + off) = *(const uint2*)(wlo + gofs);
        }
        __syncthreads();

#pragma unroll
        for (int kk = 0; kk < 2; ++kk) {
            const uint32_t kb = kk * 32;
            uint32_t ah[2][4], al[2][4];
            ldm_x4(ah[0], sbase + aOff[0] + kb);
            ldm_x4(al[0], sbase + OFF_ALO + aOff[0] + kb);
            ldm_x4(ah[1], sbase + aOff[1] + kb);
            ldm_x4(al[1], sbase + OFF_ALO + aOff[1] + kb);
#pragma unroll
            for (int g = 0; g < 4; ++g) {
                uint32_t bh[4], bl[4];
                ldm_x4(bh, sbase + OFF_WHI + bOff[g] + kb);
                ldm_x4(bl, sbase + OFF_WLO + bOff[g] + kb);
#pragma unroll
                for (int m = 0; m < 2; ++m) {
                    mma_bf16(acc[m][g * 2],     ah[m], bh);
                    mma_bf16(acc[m][g * 2],     al[m], bh);
                    mma_bf16(acc[m][g * 2],     ah[m], bl);
                    mma_bf16(acc[m][g * 2 + 1], ah[m], bh + 2);
                    mma_bf16(acc[m][g * 2 + 1], al[m], bh + 2);
                    mma_bf16(acc[m][g * 2 + 1], ah[m], bl + 2);
                }
            }
        }
    }

    const bool is_yr = (ncol0 >= 64);
    float* outp = is_yr ? yr3 : yl3;
    const int qrow = lane >> 2;
    const int qcol = (lane & 3) * 2;
#pragma unroll
    for (int m = 0; m < 2; ++m) {
        const int rA = row0 + mrow0 + m * 16 + qrow;
        const int rB = rA + 8;
#pragma unroll
        for (int g = 0; g < 8; ++g) {
            const int c0 = g * 8 + qcol;              // local col 0..63
            float b0 = 0.f, b1 = 0.f;
            if (is_yr) { b0 = bias[c0]; b1 = bias[c0 + 1]; }
            if (rA < n) {
                float2 o;
                o.x = acc[m][g][0] + b0;
                o.y = acc[m][g][1] + b1;
                *(float2*)(outp + (size_t)rA * 64 + c0) = o;
            }
            if (rB < n) {
                float2 o;
                o.x = acc[m][g][2] + b0;
                o.y = acc[m][g][3] + b1;
                *(float2*)(outp + (size_t)rB * 64 + c0) = o;
            }
        }
    }
}

// ===========================================================================
// gather+normalize (layer 3): out = l2norm(mean(w*yl3[src]) + yr3[node]), D=64
// ===========================================================================
__global__ void __launch_bounds__(256)
gather_fin(const float* __restrict__ yl, const float* __restrict__ yr,
           const int* __restrict__ rp, const int2* __restrict__ ep,
           float* __restrict__ out, int n) {
    const int node = (blockIdx.x * blockDim.x + threadIdx.x) >> 5;
    const int lane = threadIdx.x & 31;
    if (node >= n) return;

    const int s0 = rp[node];
    const int s1 = rp[node + 1];
    const float* xb = yl + lane * 2;

    float ax = 0.f, ay = 0.f;
    for (int base = s0; base < s1; base += 32) {
        const int m = min(32, s1 - base);
        int2 meta = make_int2(0, 0);
        if (lane < m) meta = ep[base + lane];
        int t = 0;
        for (; t + 2 <= m; t += 2) {
            const int   sA = __shfl_sync(0xffffffffu, meta.x, t);
            const float wA = __int_as_float(__shfl_sync(0xffffffffu, meta.y, t));
            const int   sB = __shfl_sync(0xffffffffu, meta.x, t + 1);
            const float wB = __int_as_float(__shfl_sync(0xffffffffu, meta.y, t + 1));
            const float2 vA = *(const float2*)(xb + (size_t)sA * 64);
            const float2 vB = *(const float2*)(xb + (size_t)sB * 64);
            ax += vA.x * wA + vB.x * wB;
            ay += vA.y * wA + vB.y * wB;
        }
        if (t < m) {
            const int   sA = __shfl_sync(0xffffffffu, meta.x, t);
            const float wA = __int_as_float(__shfl_sync(0xffffffffu, meta.y, t));
            const float2 vA = *(const float2*)(xb + (size_t)sA * 64);
            ax += vA.x * wA; ay += vA.y * wA;
        }
    }
    const float inv = 1.0f / fmaxf((float)(s1 - s0), 1.0f);
    const float2 r = *(const float2*)(yr + (size_t)node * 64 + lane * 2);
    float v0 = ax * inv + r.x;
    float v1 = ay * inv + r.y;
    float ss = v0 * v0 + v1 * v1;
#pragma unroll
    for (int o = 16; o; o >>= 1) ss += __shfl_xor_sync(0xffffffffu, ss, o);
    const float sc = 1.0f / fmaxf(sqrtf(ss), 1e-12f);
    float2 o;
    o.x = v0 * sc; o.y = v1 * sc;
    *(float2*)(out + (size_t)node * 64 + lane * 2) = o;
}

// ===========================================================================
extern "C" void kernel_launch(void* const* d_in, const int* in_sizes, int n_in,
                              void* d_out, int out_size) {
    const float* x    = (const float*)d_in[0];
    const int*   ei   = (const int*)d_in[1];   // int32 (JAX canonicalizes int64)
    const float* ew   = (const float*)d_in[2];
    const float* W1l  = (const float*)d_in[3];
    const float* b1   = (const float*)d_in[4];
    const float* W1r  = (const float*)d_in[5];
    const float* W2l  = (const float*)d_in[6];
    const float* b2   = (const float*)d_in[7];
    const float* W2r  = (const float*)d_in[8];
    const float* W3l  = (const float*)d_in[9];
    const float* b3   = (const float*)d_in[10];
    const float* W3r  = (const float*)d_in[11];
    const float* bn1g = (const float*)d_in[12];
    const float* bn1b = (const float*)d_in[13];
    const float* bn1m = (const float*)d_in[14];
    const float* bn1v = (const float*)d_in[15];
    const float* bn2g = (const float*)d_in[16];
    const float* bn2b = (const float*)d_in[17];
    const float* bn2m = (const float*)d_in[18];
    const float* bn2v = (const float*)d_in[19];

    const int n = in_sizes[0] / NODES_D;
    const int e = in_sizes[2];

    float *agg, *h1, *h2, *yl3, *yr3;
    int *cnti, *rp, *woff, *bsum;
    int2 *ep;
    __nv_bfloat16 *whi, *wlo;
    cudaGetSymbolAddress((void**)&agg, g_agg);
    cudaGetSymbolAddress((void**)&h1, g_h1);
    cudaGetSymbolAddress((void**)&h2, g_h2);
    cudaGetSymbolAddress((void**)&yl3, g_yl3);
    cudaGetSymbolAddress((void**)&yr3, g_yr3);
    cudaGetSymbolAddress((void**)&cnti, g_cnti);
    cudaGetSymbolAddress((void**)&rp, g_rp);
    cudaGetSymbolAddress((void**)&woff, g_woff);
    cudaGetSymbolAddress((void**)&bsum, g_bsum);
    cudaGetSymbolAddress((void**)&ep, g_ep);
    cudaGetSymbolAddress((void**)&whi, g_whi);
    cudaGetSymbolAddress((void**)&wlo, g_wlo);

    cudaFuncSetAttribute(gemm_l12,
                         cudaFuncAttributeMaxDynamicSharedMemorySize, SMEM_L12);
    cudaFuncSetAttribute(gemm_l3,
                         cudaFuncAttributeMaxDynamicSharedMemorySize, SMEM_L3);

    const int* src = ei;
    const int* dst = ei + e;

    const int eb  = (e + 255) / 256;
    const int nbk = (n + 255) / 256;
    const int nb1024 = (n + 1023) / 1024;
    const int gbk = (n + 7) / 8;            // gather: 8 warps/block
    const int gb  = (n + 127) / 128;        // gemm: 128 rows/block

    // ---- weight pre-split + CSR build ----
    wsplit_k<<<80, 256>>>(W1l, W1r, W2l, W2r, W3l, W3r, whi, wlo);
    zero_i<<<nbk, 256>>>(cnti, n);
    count_k<<<eb, 256>>>(dst, cnti, e);
    scan1_k<<<nb1024, 256>>>(cnti, rp, bsum, n);
    scan2_k<<<1, 32>>>(bsum, nb1024);
    scan3_k<<<nbk, 256>>>(rp, woff, bsum, n, e);
    fill_k<<<eb, 256>>>(src, dst, ew, woff, ep, e);

    // ---- Layer 1 ----
    gather_k<<<gbk, 256>>>(x, rp, ep, agg, n);
    gemm_l12<<<gb, 256, SMEM_L12>>>(agg, x, whi, wlo, 0, b1,
                                    bn1g, bn1b, bn1m, bn1v, h1, n);
    // ---- Layer 2 ----
    gather_k<<<gbk, 256>>>(h1, rp, ep, agg, n);
    gemm_l12<<<gb, 256, SMEM_L12>>>(agg, h1, whi, wlo, 256, b2,
                                    bn2g, bn2b, bn2m, bn2v, h2, n);
    // ---- Layer 3 (transform-first + L2 normalize) ----
    gemm_l3<<<gb, 256, SMEM_L3>>>(h2, whi, wlo, 512, b3, yl3, yr3, n);
    gather_fin<<<gbk, 256>>>(yl3, yr3, rp, ep, (float*)d_out, n);
}